// round 1
// baseline (speedup 1.0000x reference)
#include <cuda_runtime.h>
#include <math_constants.h>
#include <cstdint>

#define Bb 4
#define Ss 1024
#define Dd 1024
#define Hh 16
#define DKk 64
#define DFFf 4096
#define EPSl 1e-5f

#define X_ELEMS   ((size_t)Bb * Ss * Dd)                 // 4,194,304
#define ATT_ELEMS ((size_t)Bb * Hh * Ss * Ss)            // 67,108,864

// ---------------- scratch (static device allocations) ----------------
__device__ float g_q[X_ELEMS];
__device__ float g_k[X_ELEMS];
__device__ float g_v[X_ELEMS];
__device__ float g_ctx[X_ELEMS];
__device__ float g_t1[X_ELEMS];        // attn_out, later ff2
__device__ float g_x1[X_ELEMS];        // post-LN1 activations
__device__ float g_ffh[(size_t)Bb * Ss * DFFf];  // 64 MB relu hidden
__device__ float g_attn_fb[ATT_ELEMS]; // fallback if d_out lacks attn region
__device__ float g_x_fb[X_ELEMS];      // fallback if d_out lacks x region

// ---------------- generic tiled GEMM: C = A[M,K] @ W[K,N] + bias (opt relu) ----
template<bool RELU>
__global__ void gemm_bias_kernel(const float* __restrict__ A,
                                 const float* __restrict__ W,
                                 const float* __restrict__ bias,
                                 float* __restrict__ C,
                                 int M, int N, int K) {
    const int BM = 128, BN = 64, BK = 16;
    __shared__ float As[BK][BM + 1];
    __shared__ float Ws[BK][BN];
    const int tid = threadIdx.x;
    const int tx = tid & 15;     // 0..15 -> cols
    const int ty = tid >> 4;     // 0..15 -> rows
    const int row0 = blockIdx.y * BM;
    const int col0 = blockIdx.x * BN;

    float acc[8][4];
#pragma unroll
    for (int i = 0; i < 8; i++)
#pragma unroll
        for (int j = 0; j < 4; j++) acc[i][j] = 0.f;

    for (int k0 = 0; k0 < K; k0 += BK) {
#pragma unroll
        for (int i = 0; i < 8; i++) {            // 128x16 A tile, 8/thread
            int idx = tid + i * 256;
            int r = idx >> 4, c = idx & 15;
            As[c][r] = A[(size_t)(row0 + r) * K + k0 + c];
        }
#pragma unroll
        for (int i = 0; i < 4; i++) {            // 16x64 W tile, 4/thread
            int idx = tid + i * 256;
            int rk = idx >> 6, c = idx & 63;
            Ws[rk][c] = W[(size_t)(k0 + rk) * N + col0 + c];
        }
        __syncthreads();
#pragma unroll
        for (int kk = 0; kk < BK; kk++) {
            float a[8], b[4];
#pragma unroll
            for (int i = 0; i < 8; i++) a[i] = As[kk][ty + i * 16];
#pragma unroll
            for (int j = 0; j < 4; j++) b[j] = Ws[kk][tx + j * 16];
#pragma unroll
            for (int i = 0; i < 8; i++)
#pragma unroll
                for (int j = 0; j < 4; j++) acc[i][j] += a[i] * b[j];
        }
        __syncthreads();
    }
#pragma unroll
    for (int i = 0; i < 8; i++) {
        int r = row0 + ty + i * 16;
#pragma unroll
        for (int j = 0; j < 4; j++) {
            int c = col0 + tx + j * 16;
            float v = acc[i][j] + bias[c];
            if (RELU) v = fmaxf(v, 0.f);
            C[(size_t)r * N + c] = v;
        }
    }
}

// ---------------- attention scores: attn[b,h,q,k] = (Q_bh @ K_bh^T)/8 --------
__global__ void scores_kernel(const float* __restrict__ Q,
                              const float* __restrict__ Kmat,
                              float* __restrict__ attn) {
    // grid: (S/64 k-tiles, S/64 q-tiles, B*H)
    const int bh = blockIdx.z;
    const int b = bh >> 4, h = bh & 15;
    const int q0 = blockIdx.y * 64;
    const int k0 = blockIdx.x * 64;
    __shared__ float Qs[64][65];
    __shared__ float Ks[64][65];
    const int tid = threadIdx.x;
    const int tx = tid & 15, ty = tid >> 4;
    const float* Qb = Q + (size_t)b * Ss * Dd + (size_t)h * DKk;
    const float* Kb = Kmat + (size_t)b * Ss * Dd + (size_t)h * DKk;

#pragma unroll
    for (int i = 0; i < 16; i++) {
        int idx = tid + i * 256;
        int r = idx >> 6, d = idx & 63;
        Qs[r][d] = Qb[(size_t)(q0 + r) * Dd + d];
        Ks[r][d] = Kb[(size_t)(k0 + r) * Dd + d];
    }
    __syncthreads();

    float acc[4][4];
#pragma unroll
    for (int i = 0; i < 4; i++)
#pragma unroll
        for (int j = 0; j < 4; j++) acc[i][j] = 0.f;

#pragma unroll 8
    for (int kd = 0; kd < 64; kd++) {
        float a[4], bv[4];
#pragma unroll
        for (int i = 0; i < 4; i++) a[i] = Qs[ty + i * 16][kd];
#pragma unroll
        for (int j = 0; j < 4; j++) bv[j] = Ks[tx + j * 16][kd];
#pragma unroll
        for (int i = 0; i < 4; i++)
#pragma unroll
            for (int j = 0; j < 4; j++) acc[i][j] += a[i] * bv[j];
    }
    float* out = attn + (size_t)bh * Ss * Ss;
#pragma unroll
    for (int i = 0; i < 4; i++) {
        int r = q0 + ty + i * 16;
#pragma unroll
        for (int j = 0; j < 4; j++) {
            int c = k0 + tx + j * 16;
            out[(size_t)r * Ss + c] = acc[i][j] * 0.125f;
        }
    }
}

// ---------------- row softmax in place over last dim (1024) ------------------
__global__ void softmax_kernel(float* __restrict__ attn) {
    const size_t row = blockIdx.x;
    float* p = attn + row * Ss;
    const int tid = threadIdx.x;  // 256
    __shared__ float red[256];
    float v[4];
    float m = -CUDART_INF_F;
#pragma unroll
    for (int i = 0; i < 4; i++) { v[i] = p[tid + i * 256]; m = fmaxf(m, v[i]); }
    red[tid] = m; __syncthreads();
    for (int s = 128; s > 0; s >>= 1) {
        if (tid < s) red[tid] = fmaxf(red[tid], red[tid + s]);
        __syncthreads();
    }
    m = red[0]; __syncthreads();
    float sum = 0.f;
#pragma unroll
    for (int i = 0; i < 4; i++) { v[i] = __expf(v[i] - m); sum += v[i]; }
    red[tid] = sum; __syncthreads();
    for (int s = 128; s > 0; s >>= 1) {
        if (tid < s) red[tid] += red[tid + s];
        __syncthreads();
    }
    float inv = 1.f / red[0];
#pragma unroll
    for (int i = 0; i < 4; i++) p[tid + i * 256] = v[i] * inv;
}

// ---------------- ctx[b,q,h,:] = attn_bh[q,:] @ V_bh -------------------------
__global__ void ctx_kernel(const float* __restrict__ attn,
                           const float* __restrict__ V,
                           float* __restrict__ ctx) {
    // grid: (S/64 q-tiles, B*H)
    const int bh = blockIdx.y;
    const int b = bh >> 4, h = bh & 15;
    const int q0 = blockIdx.x * 64;
    const float* Ab = attn + (size_t)bh * Ss * Ss;
    const float* Vb = V + (size_t)b * Ss * Dd + (size_t)h * DKk;
    __shared__ float Ast[32][65];
    __shared__ float Vs[32][64];
    const int tid = threadIdx.x;
    const int tx = tid & 15, ty = tid >> 4;

    float acc[4][4];
#pragma unroll
    for (int i = 0; i < 4; i++)
#pragma unroll
        for (int j = 0; j < 4; j++) acc[i][j] = 0.f;

    for (int k0 = 0; k0 < Ss; k0 += 32) {
#pragma unroll
        for (int i = 0; i < 8; i++) {            // 64x32 A tile
            int idx = tid + i * 256;
            int r = idx >> 5, c = idx & 31;
            Ast[c][r] = Ab[(size_t)(q0 + r) * Ss + k0 + c];
        }
#pragma unroll
        for (int i = 0; i < 8; i++) {            // 32x64 V tile
            int idx = tid + i * 256;
            int kk = idx >> 6, d = idx & 63;
            Vs[kk][d] = Vb[(size_t)(k0 + kk) * Dd + d];
        }
        __syncthreads();
#pragma unroll
        for (int kk = 0; kk < 32; kk++) {
            float a[4], bv[4];
#pragma unroll
            for (int i = 0; i < 4; i++) a[i] = Ast[kk][ty + i * 16];
#pragma unroll
            for (int j = 0; j < 4; j++) bv[j] = Vs[kk][tx + j * 16];
#pragma unroll
            for (int i = 0; i < 4; i++)
#pragma unroll
                for (int j = 0; j < 4; j++) acc[i][j] += a[i] * bv[j];
        }
        __syncthreads();
    }
#pragma unroll
    for (int i = 0; i < 4; i++) {
        int r = q0 + ty + i * 16;
#pragma unroll
        for (int j = 0; j < 4; j++) {
            int c = tx + j * 16;
            ctx[((size_t)b * Ss + r) * Dd + (size_t)h * DKk + c] = acc[i][j];
        }
    }
}

// ---------------- residual add + layernorm over last dim (1024) --------------
__global__ void add_ln_kernel(const float* __restrict__ a,
                              const float* __restrict__ bres,
                              const float* __restrict__ g,
                              const float* __restrict__ be,
                              float* __restrict__ out) {
    const size_t row = blockIdx.x;
    const float* pa = a + row * Dd;
    const float* pb = bres + row * Dd;
    float* po = out + row * Dd;
    const int tid = threadIdx.x;  // 256
    __shared__ float red[256];
    float v[4];
    float s = 0.f;
#pragma unroll
    for (int i = 0; i < 4; i++) {
        int c = tid + i * 256;
        v[i] = pa[c] + pb[c];
        s += v[i];
    }
    red[tid] = s; __syncthreads();
    for (int st = 128; st > 0; st >>= 1) {
        if (tid < st) red[tid] += red[tid + st];
        __syncthreads();
    }
    const float mu = red[0] * (1.f / Dd);
    __syncthreads();
    float q = 0.f;
#pragma unroll
    for (int i = 0; i < 4; i++) { float d = v[i] - mu; q += d * d; }
    red[tid] = q; __syncthreads();
    for (int st = 128; st > 0; st >>= 1) {
        if (tid < st) red[tid] += red[tid + st];
        __syncthreads();
    }
    const float inv = rsqrtf(red[0] * (1.f / Dd) + EPSl);
    __syncthreads();
#pragma unroll
    for (int i = 0; i < 4; i++) {
        int c = tid + i * 256;
        po[c] = (v[i] - mu) * inv * g[c] + be[c];
    }
}

// ---------------- launch -----------------------------------------------------
extern "C" void kernel_launch(void* const* d_in, const int* in_sizes, int n_in,
                              void* d_out, int out_size) {
    const float* x  = (const float*)d_in[0];
    const float* Wq = (const float*)d_in[1];
    const float* bq = (const float*)d_in[2];
    const float* Wk = (const float*)d_in[3];
    const float* bk = (const float*)d_in[4];
    const float* Wv = (const float*)d_in[5];
    const float* bv = (const float*)d_in[6];
    const float* Wo = (const float*)d_in[7];
    const float* bo = (const float*)d_in[8];
    const float* W1 = (const float*)d_in[9];
    const float* b1 = (const float*)d_in[10];
    const float* W2 = (const float*)d_in[11];
    const float* b2 = (const float*)d_in[12];
    const float* g1 = (const float*)d_in[13];
    const float* be1 = (const float*)d_in[14];
    const float* g2 = (const float*)d_in[15];
    const float* be2 = (const float*)d_in[16];

    float* q;  cudaGetSymbolAddress((void**)&q,  g_q);
    float* k;  cudaGetSymbolAddress((void**)&k,  g_k);
    float* v;  cudaGetSymbolAddress((void**)&v,  g_v);
    float* ctx; cudaGetSymbolAddress((void**)&ctx, g_ctx);
    float* t1; cudaGetSymbolAddress((void**)&t1, g_t1);
    float* x1; cudaGetSymbolAddress((void**)&x1, g_x1);
    float* ffh; cudaGetSymbolAddress((void**)&ffh, g_ffh);
    float* attn_fb; cudaGetSymbolAddress((void**)&attn_fb, g_attn_fb);
    float* x_fb; cudaGetSymbolAddress((void**)&x_fb, g_x_fb);

    // route outputs based on what the harness gave us
    float* out_x;
    float* out_attn;
    const size_t osz = (size_t)out_size;
    if (osz >= X_ELEMS + ATT_ELEMS) {
        out_x = (float*)d_out;
        out_attn = (float*)d_out + X_ELEMS;
    } else if (osz == ATT_ELEMS) {
        out_x = x_fb;
        out_attn = (float*)d_out;
    } else {
        out_x = (float*)d_out;
        out_attn = attn_fb;
    }

    const int M = Bb * Ss;  // 4096
    dim3 blk(256);

    // QKV projections
    gemm_bias_kernel<false><<<dim3(Dd / 64, M / 128), blk>>>(x, Wq, bq, q, M, Dd, Dd);
    gemm_bias_kernel<false><<<dim3(Dd / 64, M / 128), blk>>>(x, Wk, bk, k, M, Dd, Dd);
    gemm_bias_kernel<false><<<dim3(Dd / 64, M / 128), blk>>>(x, Wv, bv, v, M, Dd, Dd);

    // attention
    scores_kernel<<<dim3(Ss / 64, Ss / 64, Bb * Hh), blk>>>(q, k, out_attn);
    softmax_kernel<<<(unsigned)(Bb * Hh * Ss), blk>>>(out_attn);
    ctx_kernel<<<dim3(Ss / 64, Bb * Hh), blk>>>(out_attn, v, ctx);

    // output projection + LN1
    gemm_bias_kernel<false><<<dim3(Dd / 64, M / 128), blk>>>(ctx, Wo, bo, t1, M, Dd, Dd);
    add_ln_kernel<<<M, blk>>>(x, t1, g1, be1, x1);

    // FFN + LN2
    gemm_bias_kernel<true><<<dim3(DFFf / 64, M / 128), blk>>>(x1, W1, b1, ffh, M, DFFf, Dd);
    gemm_bias_kernel<false><<<dim3(Dd / 64, M / 128), blk>>>(ffh, W2, b2, t1, M, Dd, DFFf);
    add_ln_kernel<<<M, blk>>>(x1, t1, g2, be2, out_x);
}

// round 2
// speedup vs baseline: 3.1174x; 3.1174x over previous
#include <cuda_runtime.h>
#include <math_constants.h>
#include <cstdint>

#define Bb 4
#define Ss 1024
#define Dd 1024
#define Hh 16
#define DKk 64
#define DFFf 4096
#define EPSl 1e-5f

#define X_ELEMS   ((size_t)Bb * Ss * Dd)                 // 4,194,304
#define ATT_ELEMS ((size_t)Bb * Hh * Ss * Ss)            // 67,108,864

// ---------------- scratch (static device allocations) ----------------
__device__ float g_q[X_ELEMS];
__device__ float g_k[X_ELEMS];
__device__ float g_v[X_ELEMS];
__device__ float g_ctx[X_ELEMS];
__device__ float g_t1[X_ELEMS];
__device__ float g_x1[X_ELEMS];
__device__ float g_ffh[(size_t)Bb * Ss * DFFf];
__device__ float g_attn_fb[ATT_ELEMS];
__device__ float g_x_fb[X_ELEMS];

// ---------------- tf32 helpers ----------------
__device__ __forceinline__ uint32_t f2tf(float x) {
    uint32_t r;
    asm("cvt.rna.tf32.f32 %0, %1;" : "=r"(r) : "f"(x));
    return r;
}

__device__ __forceinline__ void mma_tf32(float c[4], const uint32_t a[4], const uint32_t b[2]) {
    asm volatile(
        "mma.sync.aligned.m16n8k8.row.col.f32.tf32.tf32.f32 "
        "{%0,%1,%2,%3}, {%4,%5,%6,%7}, {%8,%9}, {%0,%1,%2,%3};"
        : "+f"(c[0]), "+f"(c[1]), "+f"(c[2]), "+f"(c[3])
        : "r"(a[0]), "r"(a[1]), "r"(a[2]), "r"(a[3]), "r"(b[0]), "r"(b[1]));
}

// MODE: 0 = plain GEMM (z unused). 1 = attention scores (A=Q head, B^T=K head,
// C=attn[z]). 2 = ctx (A=attn[z], B=V head, C=ctx head slice).
template<int BM, int BN, int WM, int WN, bool TRANSB, bool BIAS, bool RELU, int MODE>
__global__ void __launch_bounds__(256)
tf32_gemm(const float* __restrict__ A, const float* __restrict__ B,
          const float* __restrict__ bias, float* __restrict__ C,
          int K, int lda, int ldb, int ldc, float scale) {
    constexpr int BK = 16;
    constexpr int WCOLS = BN / WN;
    constexpr int AM = WM / 16;
    constexpr int BNT = WN / 8;
    constexpr int LDA_V = BM * BK / (4 * 256);   // float4 loads of A per thread
    constexpr int LDB_V = BK * BN / (4 * 256);   // float4 loads of B per thread

    __shared__ float As[2][BK][BM + 8];
    __shared__ float Bs[2][BK][BN + 8];

    const int tid = threadIdx.x;
    const int warp = tid >> 5, lane = tid & 31;
    const int grp = lane >> 2, tig = lane & 3;
    const int wm = (warp / WCOLS) * WM;
    const int wn = (warp % WCOLS) * WN;
    const int row0 = blockIdx.y * BM;
    const int col0 = blockIdx.x * BN;
    const int z = blockIdx.z;

    size_t offA = 0, offB = 0, offC = 0;
    if (MODE == 1) {
        size_t ho = (size_t)(z >> 4) * Ss * Dd + (size_t)(z & 15) * DKk;
        offA = ho; offB = ho; offC = (size_t)z * Ss * Ss;
    }
    if (MODE == 2) {
        size_t ho = (size_t)(z >> 4) * Ss * Dd + (size_t)(z & 15) * DKk;
        offA = (size_t)z * Ss * Ss; offB = ho; offC = ho;
    }
    const float* Ag = A + offA;
    const float* Bg = B + offB;
    float* Cg = C + offC;

    float4 ra[LDA_V];
    float4 rb[LDB_V];

    auto loadA = [&](int k0) {
#pragma unroll
        for (int i = 0; i < LDA_V; i++) {
            int flat = tid + i * 256;
            int r = flat >> 2, c4 = flat & 3;
            ra[i] = *(const float4*)&Ag[(size_t)(row0 + r) * lda + k0 + c4 * 4];
        }
    };
    auto loadB = [&](int k0) {
#pragma unroll
        for (int i = 0; i < LDB_V; i++) {
            int flat = tid + i * 256;
            if (!TRANSB) {
                constexpr int C4 = BN / 4;
                int r = flat / C4, c4 = flat % C4;
                rb[i] = *(const float4*)&Bg[(size_t)(k0 + r) * ldb + col0 + c4 * 4];
            } else {
                int n = flat >> 2, k4 = flat & 3;
                rb[i] = *(const float4*)&Bg[(size_t)(col0 + n) * ldb + k0 + k4 * 4];
            }
        }
    };
    auto storeA = [&](int buf) {
#pragma unroll
        for (int i = 0; i < LDA_V; i++) {
            int flat = tid + i * 256;
            int r = flat >> 2, c4 = flat & 3;
            As[buf][c4 * 4 + 0][r] = __uint_as_float(f2tf(ra[i].x));
            As[buf][c4 * 4 + 1][r] = __uint_as_float(f2tf(ra[i].y));
            As[buf][c4 * 4 + 2][r] = __uint_as_float(f2tf(ra[i].z));
            As[buf][c4 * 4 + 3][r] = __uint_as_float(f2tf(ra[i].w));
        }
    };
    auto storeB = [&](int buf) {
#pragma unroll
        for (int i = 0; i < LDB_V; i++) {
            int flat = tid + i * 256;
            if (!TRANSB) {
                constexpr int C4 = BN / 4;
                int r = flat / C4, c4 = flat % C4;
                Bs[buf][r][c4 * 4 + 0] = __uint_as_float(f2tf(rb[i].x));
                Bs[buf][r][c4 * 4 + 1] = __uint_as_float(f2tf(rb[i].y));
                Bs[buf][r][c4 * 4 + 2] = __uint_as_float(f2tf(rb[i].z));
                Bs[buf][r][c4 * 4 + 3] = __uint_as_float(f2tf(rb[i].w));
            } else {
                int n = flat >> 2, k4 = flat & 3;
                Bs[buf][k4 * 4 + 0][n] = __uint_as_float(f2tf(rb[i].x));
                Bs[buf][k4 * 4 + 1][n] = __uint_as_float(f2tf(rb[i].y));
                Bs[buf][k4 * 4 + 2][n] = __uint_as_float(f2tf(rb[i].z));
                Bs[buf][k4 * 4 + 3][n] = __uint_as_float(f2tf(rb[i].w));
            }
        }
    };

    float acc[AM][BNT][4];
#pragma unroll
    for (int i = 0; i < AM; i++)
#pragma unroll
        for (int j = 0; j < BNT; j++)
#pragma unroll
            for (int q = 0; q < 4; q++) acc[i][j][q] = 0.f;

    const int KT = K / BK;
    loadA(0); loadB(0);
    storeA(0); storeB(0);
    __syncthreads();

    int buf = 0;
    for (int kt = 0; kt < KT; kt++) {
        if (kt + 1 < KT) { loadA((kt + 1) * BK); loadB((kt + 1) * BK); }
#pragma unroll
        for (int ks = 0; ks < BK; ks += 8) {
            uint32_t af[AM][4];
            uint32_t bf[BNT][2];
#pragma unroll
            for (int i = 0; i < AM; i++) {
                af[i][0] = __float_as_uint(As[buf][ks + tig][wm + i * 16 + grp]);
                af[i][1] = __float_as_uint(As[buf][ks + tig][wm + i * 16 + grp + 8]);
                af[i][2] = __float_as_uint(As[buf][ks + tig + 4][wm + i * 16 + grp]);
                af[i][3] = __float_as_uint(As[buf][ks + tig + 4][wm + i * 16 + grp + 8]);
            }
#pragma unroll
            for (int j = 0; j < BNT; j++) {
                bf[j][0] = __float_as_uint(Bs[buf][ks + tig][wn + j * 8 + grp]);
                bf[j][1] = __float_as_uint(Bs[buf][ks + tig + 4][wn + j * 8 + grp]);
            }
#pragma unroll
            for (int i = 0; i < AM; i++)
#pragma unroll
                for (int j = 0; j < BNT; j++)
                    mma_tf32(acc[i][j], af[i], bf[j]);
        }
        if (kt + 1 < KT) { storeA(buf ^ 1); storeB(buf ^ 1); __syncthreads(); }
        buf ^= 1;
    }

#pragma unroll
    for (int i = 0; i < AM; i++) {
        int r1 = row0 + wm + i * 16 + grp;
        int r2 = r1 + 8;
#pragma unroll
        for (int j = 0; j < BNT; j++) {
            int cc = col0 + wn + j * 8 + tig * 2;
            float b0v = 0.f, b1v = 0.f;
            if (BIAS) { b0v = bias[cc]; b1v = bias[cc + 1]; }
            float v0 = acc[i][j][0] * scale + b0v;
            float v1 = acc[i][j][1] * scale + b1v;
            float v2 = acc[i][j][2] * scale + b0v;
            float v3 = acc[i][j][3] * scale + b1v;
            if (RELU) {
                v0 = fmaxf(v0, 0.f); v1 = fmaxf(v1, 0.f);
                v2 = fmaxf(v2, 0.f); v3 = fmaxf(v3, 0.f);
            }
            *(float2*)&Cg[(size_t)r1 * ldc + cc] = make_float2(v0, v1);
            *(float2*)&Cg[(size_t)r2 * ldc + cc] = make_float2(v2, v3);
        }
    }
}

// ---------------- row softmax in place over last dim (1024) ------------------
__global__ void softmax_kernel(float* __restrict__ attn) {
    const size_t row = blockIdx.x;
    float* p = attn + row * Ss;
    const int tid = threadIdx.x;  // 256
    __shared__ float red[256];
    float v[4];
    float m = -CUDART_INF_F;
#pragma unroll
    for (int i = 0; i < 4; i++) { v[i] = p[tid + i * 256]; m = fmaxf(m, v[i]); }
    red[tid] = m; __syncthreads();
    for (int s = 128; s > 0; s >>= 1) {
        if (tid < s) red[tid] = fmaxf(red[tid], red[tid + s]);
        __syncthreads();
    }
    m = red[0]; __syncthreads();
    float sum = 0.f;
#pragma unroll
    for (int i = 0; i < 4; i++) { v[i] = __expf(v[i] - m); sum += v[i]; }
    red[tid] = sum; __syncthreads();
    for (int s = 128; s > 0; s >>= 1) {
        if (tid < s) red[tid] += red[tid + s];
        __syncthreads();
    }
    float inv = 1.f / red[0];
#pragma unroll
    for (int i = 0; i < 4; i++) p[tid + i * 256] = v[i] * inv;
}

// ---------------- residual add + layernorm over last dim (1024) --------------
__global__ void add_ln_kernel(const float* __restrict__ a,
                              const float* __restrict__ bres,
                              const float* __restrict__ g,
                              const float* __restrict__ be,
                              float* __restrict__ out) {
    const size_t row = blockIdx.x;
    const float* pa = a + row * Dd;
    const float* pb = bres + row * Dd;
    float* po = out + row * Dd;
    const int tid = threadIdx.x;  // 256
    __shared__ float red[256];
    float v[4];
    float s = 0.f;
#pragma unroll
    for (int i = 0; i < 4; i++) {
        int c = tid + i * 256;
        v[i] = pa[c] + pb[c];
        s += v[i];
    }
    red[tid] = s; __syncthreads();
    for (int st = 128; st > 0; st >>= 1) {
        if (tid < st) red[tid] += red[tid + st];
        __syncthreads();
    }
    const float mu = red[0] * (1.f / Dd);
    __syncthreads();
    float q = 0.f;
#pragma unroll
    for (int i = 0; i < 4; i++) { float d = v[i] - mu; q += d * d; }
    red[tid] = q; __syncthreads();
    for (int st = 128; st > 0; st >>= 1) {
        if (tid < st) red[tid] += red[tid + st];
        __syncthreads();
    }
    const float inv = rsqrtf(red[0] * (1.f / Dd) + EPSl);
    __syncthreads();
#pragma unroll
    for (int i = 0; i < 4; i++) {
        int c = tid + i * 256;
        po[c] = (v[i] - mu) * inv * g[c] + be[c];
    }
}

// ---------------- launch -----------------------------------------------------
extern "C" void kernel_launch(void* const* d_in, const int* in_sizes, int n_in,
                              void* d_out, int out_size) {
    const float* x  = (const float*)d_in[0];
    const float* Wq = (const float*)d_in[1];
    const float* bq = (const float*)d_in[2];
    const float* Wk = (const float*)d_in[3];
    const float* bk = (const float*)d_in[4];
    const float* Wv = (const float*)d_in[5];
    const float* bv = (const float*)d_in[6];
    const float* Wo = (const float*)d_in[7];
    const float* bo = (const float*)d_in[8];
    const float* W1 = (const float*)d_in[9];
    const float* b1 = (const float*)d_in[10];
    const float* W2 = (const float*)d_in[11];
    const float* b2 = (const float*)d_in[12];
    const float* g1 = (const float*)d_in[13];
    const float* be1 = (const float*)d_in[14];
    const float* g2 = (const float*)d_in[15];
    const float* be2 = (const float*)d_in[16];

    float* q;   cudaGetSymbolAddress((void**)&q,   g_q);
    float* k;   cudaGetSymbolAddress((void**)&k,   g_k);
    float* v;   cudaGetSymbolAddress((void**)&v,   g_v);
    float* ctx; cudaGetSymbolAddress((void**)&ctx, g_ctx);
    float* t1;  cudaGetSymbolAddress((void**)&t1,  g_t1);
    float* x1;  cudaGetSymbolAddress((void**)&x1,  g_x1);
    float* ffh; cudaGetSymbolAddress((void**)&ffh, g_ffh);
    float* attn_fb; cudaGetSymbolAddress((void**)&attn_fb, g_attn_fb);
    float* x_fb;    cudaGetSymbolAddress((void**)&x_fb,    g_x_fb);

    float* out_x;
    float* out_attn;
    const size_t osz = (size_t)out_size;
    if (osz >= X_ELEMS + ATT_ELEMS) {
        out_x = (float*)d_out;
        out_attn = (float*)d_out + X_ELEMS;
    } else if (osz == ATT_ELEMS) {
        out_x = x_fb;
        out_attn = (float*)d_out;
    } else {
        out_x = (float*)d_out;
        out_attn = attn_fb;
    }

    const int M = Bb * Ss;  // 4096
    dim3 blk(256);

    // QKV projections: [4096,1024] = [4096,1024] @ [1024,1024]
    tf32_gemm<128,128,64,32,false,true,false,0><<<dim3(Dd/128, M/128), blk>>>(
        x, Wq, bq, q, Dd, Dd, Dd, Dd, 1.f);
    tf32_gemm<128,128,64,32,false,true,false,0><<<dim3(Dd/128, M/128), blk>>>(
        x, Wk, bk, k, Dd, Dd, Dd, Dd, 1.f);
    tf32_gemm<128,128,64,32,false,true,false,0><<<dim3(Dd/128, M/128), blk>>>(
        x, Wv, bv, v, Dd, Dd, Dd, Dd, 1.f);

    // scores: per (b,h): [1024,64] @ [1024,64]^T / 8
    tf32_gemm<128,128,64,32,true,false,false,1><<<dim3(Ss/128, Ss/128, Bb*Hh), blk>>>(
        q, k, nullptr, out_attn, DKk, Dd, Dd, Ss, 0.125f);

    softmax_kernel<<<(unsigned)(Bb * Hh * Ss), blk>>>(out_attn);

    // ctx: per (b,h): [1024,1024] @ [1024,64]
    tf32_gemm<128,64,64,16,false,false,false,2><<<dim3(1, Ss/128, Bb*Hh), blk>>>(
        out_attn, v, nullptr, ctx, Ss, Ss, Dd, Dd, 1.f);

    // output projection + LN1
    tf32_gemm<128,128,64,32,false,true,false,0><<<dim3(Dd/128, M/128), blk>>>(
        ctx, Wo, bo, t1, Dd, Dd, Dd, Dd, 1.f);
    add_ln_kernel<<<M, blk>>>(x, t1, g1, be1, x1);

    // FFN + LN2
    tf32_gemm<128,128,64,32,false,true,true,0><<<dim3(DFFf/128, M/128), blk>>>(
        x1, W1, b1, ffh, Dd, Dd, DFFf, DFFf, 1.f);
    tf32_gemm<128,128,64,32,false,true,false,0><<<dim3(Dd/128, M/128), blk>>>(
        ffh, W2, b2, t1, DFFf, DFFf, Dd, Dd, 1.f);
    add_ln_kernel<<<M, blk>>>(x1, t1, g2, be2, out_x);
}

// round 3
// speedup vs baseline: 3.6242x; 1.1626x over previous
#include <cuda_runtime.h>
#include <math_constants.h>
#include <cstdint>

#define Bb 4
#define Ss 1024
#define Dd 1024
#define Hh 16
#define DKk 64
#define DFFf 4096
#define EPSl 1e-5f

#define X_ELEMS   ((size_t)Bb * Ss * Dd)
#define ATT_ELEMS ((size_t)Bb * Hh * Ss * Ss)

// ---------------- scratch ----------------
__device__ float g_q[X_ELEMS];
__device__ float g_k[X_ELEMS];
__device__ float g_v[X_ELEMS];
__device__ float g_ctx[X_ELEMS];
__device__ float g_t1[X_ELEMS];
__device__ float g_x1[X_ELEMS];
__device__ float g_ffh[(size_t)Bb * Ss * DFFf];
__device__ float g_attn_fb[ATT_ELEMS];
__device__ float g_x_fb[X_ELEMS];

// ---------------- async copy helpers ----------------
__device__ __forceinline__ void cp_async16(void* smem_dst, const void* gsrc) {
    uint32_t s = (uint32_t)__cvta_generic_to_shared(smem_dst);
    asm volatile("cp.async.cg.shared.global [%0], [%1], 16;" :: "r"(s), "l"(gsrc));
}
__device__ __forceinline__ void cp_commit() {
    asm volatile("cp.async.commit_group;");
}
template<int N>
__device__ __forceinline__ void cp_wait() {
    asm volatile("cp.async.wait_group %0;" :: "n"(N));
}

__device__ __forceinline__ void mma_tf32(float c[4], const uint32_t a[4], const uint32_t b[2]) {
    asm volatile(
        "mma.sync.aligned.m16n8k8.row.col.f32.tf32.tf32.f32 "
        "{%0,%1,%2,%3}, {%4,%5,%6,%7}, {%8,%9}, {%0,%1,%2,%3};"
        : "+f"(c[0]), "+f"(c[1]), "+f"(c[2]), "+f"(c[3])
        : "r"(a[0]), "r"(a[1]), "r"(a[2]), "r"(a[3]), "r"(b[0]), "r"(b[1]));
}

// MODE: 0 = plain GEMM. 1 = scores (A=Q head, B^T=K head, C=attn[z]).
// 2 = ctx (A=attn[z], B=V head, C=ctx head slice).
template<int BM, int BN, int WM, int WN, bool TRANSB, bool BIAS, bool RELU, int MODE>
__global__ void __launch_bounds__(256)
tf32_gemm(const float* __restrict__ A, const float* __restrict__ B,
          const float* __restrict__ bias, float* __restrict__ C,
          int K, int lda, int ldb, int ldc, float scale) {
    constexpr int BK = 16;
    constexpr int STAGES = 4;
    constexpr int WCOLS = BN / WN;
    constexpr int AM = WM / 16;
    constexpr int BNT = WN / 8;
    constexpr int ASTRIDE = BK + 4;                       // 20 floats (80B, 16B-aligned)
    constexpr int BSTRIDE = TRANSB ? (BK + 4) : (BN + 4); // 20 or BN+4
    constexpr int SA = BM * ASTRIDE;                      // floats per A stage
    constexpr int SB = TRANSB ? (BN * ASTRIDE) : (BK * (BN + 4));
    constexpr int LDA_V = BM * BK / (4 * 256);
    constexpr int LDB_V = (TRANSB ? BN * BK : BK * BN) / (4 * 256);

    extern __shared__ float smem[];
    float* As = smem;                 // [STAGES][BM][ASTRIDE]
    float* Bs = smem + STAGES * SA;   // [STAGES][...]

    const int tid = threadIdx.x;
    const int warp = tid >> 5, lane = tid & 31;
    const int grp = lane >> 2, tig = lane & 3;
    const int wm = (warp / WCOLS) * WM;
    const int wn = (warp % WCOLS) * WN;
    const int row0 = blockIdx.y * BM;
    const int col0 = blockIdx.x * BN;
    const int z = blockIdx.z;

    size_t offA = 0, offB = 0, offC = 0;
    if (MODE == 1) {
        size_t ho = (size_t)(z >> 4) * Ss * Dd + (size_t)(z & 15) * DKk;
        offA = ho; offB = ho; offC = (size_t)z * Ss * Ss;
    }
    if (MODE == 2) {
        size_t ho = (size_t)(z >> 4) * Ss * Dd + (size_t)(z & 15) * DKk;
        offA = (size_t)z * Ss * Ss; offB = ho; offC = ho;
    }
    const float* Ag = A + offA;
    const float* Bg = B + offB;
    float* Cg = C + offC;

    auto copyA = [&](int stage, int k0) {
#pragma unroll
        for (int i = 0; i < LDA_V; i++) {
            int flat = tid + i * 256;
            int r = flat >> 2, c4 = flat & 3;
            cp_async16(&As[stage * SA + r * ASTRIDE + c4 * 4],
                       &Ag[(size_t)(row0 + r) * lda + k0 + c4 * 4]);
        }
    };
    auto copyB = [&](int stage, int k0) {
#pragma unroll
        for (int i = 0; i < LDB_V; i++) {
            int flat = tid + i * 256;
            if (TRANSB) {
                int n = flat >> 2, c4 = flat & 3;
                cp_async16(&Bs[stage * SB + n * BSTRIDE + c4 * 4],
                           &Bg[(size_t)(col0 + n) * ldb + k0 + c4 * 4]);
            } else {
                constexpr int C4 = BN / 4;
                int r = flat / C4, c4 = flat % C4;
                cp_async16(&Bs[stage * SB + r * BSTRIDE + c4 * 4],
                           &Bg[(size_t)(k0 + r) * ldb + col0 + c4 * 4]);
            }
        }
    };

    float acc[AM][BNT][4];
#pragma unroll
    for (int i = 0; i < AM; i++)
#pragma unroll
        for (int j = 0; j < BNT; j++)
#pragma unroll
            for (int q = 0; q < 4; q++) acc[i][j][q] = 0.f;

    const int KT = K / BK;   // always >= STAGES-1 for our shapes
    int fetch = 0;
    for (; fetch < STAGES - 1; fetch++) {
        copyA(fetch, fetch * BK);
        copyB(fetch, fetch * BK);
        cp_commit();
    }

    for (int kt = 0; kt < KT; kt++) {
        cp_wait<STAGES - 2>();
        __syncthreads();
        if (fetch < KT) {
            copyA(fetch % STAGES, fetch * BK);
            copyB(fetch % STAGES, fetch * BK);
            fetch++;
        }
        cp_commit();

        const int buf = kt % STAGES;
        const float* Asb = &As[buf * SA];
        const float* Bsb = &Bs[buf * SB];
#pragma unroll
        for (int ks = 0; ks < BK; ks += 8) {
            uint32_t af[AM][4];
            uint32_t bf[BNT][2];
#pragma unroll
            for (int i = 0; i < AM; i++) {
                int m = wm + i * 16 + grp;
                af[i][0] = __float_as_uint(Asb[m * ASTRIDE + ks + tig]);
                af[i][1] = __float_as_uint(Asb[(m + 8) * ASTRIDE + ks + tig]);
                af[i][2] = __float_as_uint(Asb[m * ASTRIDE + ks + tig + 4]);
                af[i][3] = __float_as_uint(Asb[(m + 8) * ASTRIDE + ks + tig + 4]);
            }
#pragma unroll
            for (int j = 0; j < BNT; j++) {
                int n = wn + j * 8 + grp;
                if (TRANSB) {
                    bf[j][0] = __float_as_uint(Bsb[n * BSTRIDE + ks + tig]);
                    bf[j][1] = __float_as_uint(Bsb[n * BSTRIDE + ks + tig + 4]);
                } else {
                    bf[j][0] = __float_as_uint(Bsb[(ks + tig) * BSTRIDE + n]);
                    bf[j][1] = __float_as_uint(Bsb[(ks + tig + 4) * BSTRIDE + n]);
                }
            }
#pragma unroll
            for (int i = 0; i < AM; i++)
#pragma unroll
                for (int j = 0; j < BNT; j++)
                    mma_tf32(acc[i][j], af[i], bf[j]);
        }
    }

#pragma unroll
    for (int i = 0; i < AM; i++) {
        int r1 = row0 + wm + i * 16 + grp;
        int r2 = r1 + 8;
#pragma unroll
        for (int j = 0; j < BNT; j++) {
            int cc = col0 + wn + j * 8 + tig * 2;
            float b0v = 0.f, b1v = 0.f;
            if (BIAS) { b0v = bias[cc]; b1v = bias[cc + 1]; }
            float v0 = acc[i][j][0] * scale + b0v;
            float v1 = acc[i][j][1] * scale + b1v;
            float v2 = acc[i][j][2] * scale + b0v;
            float v3 = acc[i][j][3] * scale + b1v;
            if (RELU) {
                v0 = fmaxf(v0, 0.f); v1 = fmaxf(v1, 0.f);
                v2 = fmaxf(v2, 0.f); v3 = fmaxf(v3, 0.f);
            }
            *(float2*)&Cg[(size_t)r1 * ldc + cc] = make_float2(v0, v1);
            *(float2*)&Cg[(size_t)r2 * ldc + cc] = make_float2(v2, v3);
        }
    }
}

// ---------------- row softmax (1024 cols, float4 + warp shuffles) ------------
__global__ void softmax_kernel(float* __restrict__ attn) {
    const size_t row = blockIdx.x;
    float4* p = (float4*)(attn + row * Ss);
    const int tid = threadIdx.x;  // 256
    __shared__ float red[8];
    float4 v = p[tid];
    float m = fmaxf(fmaxf(v.x, v.y), fmaxf(v.z, v.w));
#pragma unroll
    for (int o = 16; o > 0; o >>= 1) m = fmaxf(m, __shfl_xor_sync(~0u, m, o));
    if ((tid & 31) == 0) red[tid >> 5] = m;
    __syncthreads();
    m = red[tid & 7];
#pragma unroll
    for (int o = 4; o > 0; o >>= 1) m = fmaxf(m, __shfl_xor_sync(~0u, m, o));
    v.x = __expf(v.x - m); v.y = __expf(v.y - m);
    v.z = __expf(v.z - m); v.w = __expf(v.w - m);
    float s = v.x + v.y + v.z + v.w;
#pragma unroll
    for (int o = 16; o > 0; o >>= 1) s += __shfl_xor_sync(~0u, s, o);
    __syncthreads();
    if ((tid & 31) == 0) red[tid >> 5] = s;
    __syncthreads();
    s = red[tid & 7];
#pragma unroll
    for (int o = 4; o > 0; o >>= 1) s += __shfl_xor_sync(~0u, s, o);
    float inv = 1.f / s;
    v.x *= inv; v.y *= inv; v.z *= inv; v.w *= inv;
    p[tid] = v;
}

// ---------------- residual add + layernorm (1024 cols) -----------------------
__global__ void add_ln_kernel(const float* __restrict__ a,
                              const float* __restrict__ bres,
                              const float* __restrict__ g,
                              const float* __restrict__ be,
                              float* __restrict__ out) {
    const size_t row = blockIdx.x;
    const float4* pa = (const float4*)(a + row * Dd);
    const float4* pb = (const float4*)(bres + row * Dd);
    float4* po = (float4*)(out + row * Dd);
    const int tid = threadIdx.x;  // 256
    __shared__ float red[8];
    float4 va = pa[tid], vb = pb[tid];
    float4 v = make_float4(va.x + vb.x, va.y + vb.y, va.z + vb.z, va.w + vb.w);
    float s = v.x + v.y + v.z + v.w;
#pragma unroll
    for (int o = 16; o > 0; o >>= 1) s += __shfl_xor_sync(~0u, s, o);
    if ((tid & 31) == 0) red[tid >> 5] = s;
    __syncthreads();
    s = red[tid & 7];
#pragma unroll
    for (int o = 4; o > 0; o >>= 1) s += __shfl_xor_sync(~0u, s, o);
    const float mu = s * (1.f / Dd);
    float q = (v.x - mu) * (v.x - mu) + (v.y - mu) * (v.y - mu)
            + (v.z - mu) * (v.z - mu) + (v.w - mu) * (v.w - mu);
#pragma unroll
    for (int o = 16; o > 0; o >>= 1) q += __shfl_xor_sync(~0u, q, o);
    __syncthreads();
    if ((tid & 31) == 0) red[tid >> 5] = q;
    __syncthreads();
    q = red[tid & 7];
#pragma unroll
    for (int o = 4; o > 0; o >>= 1) q += __shfl_xor_sync(~0u, q, o);
    const float inv = rsqrtf(q * (1.f / Dd) + EPSl);
    float4 vg = ((const float4*)g)[tid], vbe = ((const float4*)be)[tid];
    po[row ? tid : tid] = make_float4((v.x - mu) * inv * vg.x + vbe.x,
                                      (v.y - mu) * inv * vg.y + vbe.y,
                                      (v.z - mu) * inv * vg.z + vbe.z,
                                      (v.w - mu) * inv * vg.w + vbe.w);
}

// ---------------- launch ------------------------------------------------------
extern "C" void kernel_launch(void* const* d_in, const int* in_sizes, int n_in,
                              void* d_out, int out_size) {
    const float* x  = (const float*)d_in[0];
    const float* Wq = (const float*)d_in[1];
    const float* bq = (const float*)d_in[2];
    const float* Wk = (const float*)d_in[3];
    const float* bk = (const float*)d_in[4];
    const float* Wv = (const float*)d_in[5];
    const float* bv = (const float*)d_in[6];
    const float* Wo = (const float*)d_in[7];
    const float* bo = (const float*)d_in[8];
    const float* W1 = (const float*)d_in[9];
    const float* b1 = (const float*)d_in[10];
    const float* W2 = (const float*)d_in[11];
    const float* b2 = (const float*)d_in[12];
    const float* g1 = (const float*)d_in[13];
    const float* be1 = (const float*)d_in[14];
    const float* g2 = (const float*)d_in[15];
    const float* be2 = (const float*)d_in[16];

    float* q;   cudaGetSymbolAddress((void**)&q,   g_q);
    float* k;   cudaGetSymbolAddress((void**)&k,   g_k);
    float* v;   cudaGetSymbolAddress((void**)&v,   g_v);
    float* ctx; cudaGetSymbolAddress((void**)&ctx, g_ctx);
    float* t1;  cudaGetSymbolAddress((void**)&t1,  g_t1);
    float* x1;  cudaGetSymbolAddress((void**)&x1,  g_x1);
    float* ffh; cudaGetSymbolAddress((void**)&ffh, g_ffh);
    float* attn_fb; cudaGetSymbolAddress((void**)&attn_fb, g_attn_fb);
    float* x_fb;    cudaGetSymbolAddress((void**)&x_fb,    g_x_fb);

    float* out_x;
    float* out_attn;
    const size_t osz = (size_t)out_size;
    if (osz >= X_ELEMS + ATT_ELEMS) {
        out_x = (float*)d_out;
        out_attn = (float*)d_out + X_ELEMS;
    } else if (osz == ATT_ELEMS) {
        out_x = x_fb;
        out_attn = (float*)d_out;
    } else {
        out_x = (float*)d_out;
        out_attn = attn_fb;
    }

    const int M = Bb * Ss;  // 4096
    dim3 blk(256);

    // dynamic smem sizes (floats): STAGES*(BM*20 + stageB) * 4 bytes
    const int smem_proj   = 4 * (128 * 20 + 16 * 132) * 4;  // 74,752 B
    const int smem_scores = 4 * (128 * 20 + 128 * 20) * 4;  // 81,920 B
    const int smem_ctx    = 4 * (128 * 20 + 16 * 68) * 4;   // 58,368 B

    auto* kproj  = tf32_gemm<128,128,64,32,false,true,false,0>;
    auto* kprojr = tf32_gemm<128,128,64,32,false,true,true,0>;
    auto* kscore = tf32_gemm<128,128,64,32,true,false,false,1>;
    auto* kctx   = tf32_gemm<128,64,64,16,false,false,false,2>;
    cudaFuncSetAttribute(kproj,  cudaFuncAttributeMaxDynamicSharedMemorySize, smem_proj);
    cudaFuncSetAttribute(kprojr, cudaFuncAttributeMaxDynamicSharedMemorySize, smem_proj);
    cudaFuncSetAttribute(kscore, cudaFuncAttributeMaxDynamicSharedMemorySize, smem_scores);
    cudaFuncSetAttribute(kctx,   cudaFuncAttributeMaxDynamicSharedMemorySize, smem_ctx);

    // QKV projections
    kproj<<<dim3(Dd/128, M/128), blk, smem_proj>>>(x, Wq, bq, q, Dd, Dd, Dd, Dd, 1.f);
    kproj<<<dim3(Dd/128, M/128), blk, smem_proj>>>(x, Wk, bk, k, Dd, Dd, Dd, Dd, 1.f);
    kproj<<<dim3(Dd/128, M/128), blk, smem_proj>>>(x, Wv, bv, v, Dd, Dd, Dd, Dd, 1.f);

    // scores: per (b,h): [1024,64] @ [1024,64]^T / 8
    kscore<<<dim3(Ss/128, Ss/128, Bb*Hh), blk, smem_scores>>>(
        q, k, nullptr, out_attn, DKk, Dd, Dd, Ss, 0.125f);

    softmax_kernel<<<(unsigned)(Bb * Hh * Ss), blk>>>(out_attn);

    // ctx: per (b,h): [1024,1024] @ [1024,64]
    kctx<<<dim3(1, Ss/128, Bb*Hh), blk, smem_ctx>>>(
        out_attn, v, nullptr, ctx, Ss, Ss, Dd, Dd, 1.f);

    // output projection + LN1
    kproj<<<dim3(Dd/128, M/128), blk, smem_proj>>>(ctx, Wo, bo, t1, Dd, Dd, Dd, Dd, 1.f);
    add_ln_kernel<<<M, blk>>>(x, t1, g1, be1, x1);

    // FFN + LN2
    kprojr<<<dim3(DFFf/128, M/128), blk, smem_proj>>>(x1, W1, b1, ffh, Dd, Dd, DFFf, DFFf, 1.f);
    kproj<<<dim3(Dd/128, M/128), blk, smem_proj>>>(ffh, W2, b2, t1, DFFf, DFFf, Dd, Dd, 1.f);
    add_ln_kernel<<<M, blk>>>(x1, t1, g2, be2, out_x);
}